// round 15
// baseline (speedup 1.0000x reference)
#include <cuda_runtime.h>
#include <cuda_bf16.h>
#include <cstdint>

// ---------------------------------------------------------------------------
// HRR self-attention:
//   GEMM1 (mma.sync bf16 x3-split): F = x @ (W_qkv . DFT)   [fp32 out]
//   chunked complex scan: Spec = cumsum_s(Fk*Fv) * conj(Fq) -> bf16 split A2
//   GEMM2 (mma.sync bf16 x3-split): out = Spec @ (iDFT . W_out)
// Engine: HMMA m16n8k16 bf16, BM=BN=128, 256 threads, occupancy 2.
// ---------------------------------------------------------------------------

#define BATCH 4
#define SEQ   4096
#define DMODEL 1024
#define NHEAD 8
#define NF    65
#define NROWS 16384
#define NP1   3200          // GEMM1 N (3120 used, padded to 25*128)
#define KA1   3072          // GEMM1 K' = 3*1024
#define NPAD2 1056          // GEMM2 base K padded (1040 used, 33*32)
#define KA2   3168          // GEMM2 K' = 3*1056
#define NC2   1040
#define CHUNKS 32
#define CLEN   128

// ---------------- scratch (static device globals; zero-initialized) --------
__device__ __align__(16) float  g_Wf1[(size_t)DMODEL * NP1];
__device__ __align__(16) float  g_Wf2[(size_t)NPAD2 * DMODEL];
__device__ __align__(16) float  g_F  [(size_t)NROWS * NP1];
__device__ __align__(16) __nv_bfloat16 g_A1[(size_t)NROWS * KA1];
__device__ __align__(16) __nv_bfloat16 g_B1[(size_t)NP1   * KA1];
__device__ __align__(16) __nv_bfloat16 g_A2[(size_t)NROWS * KA2];
__device__ __align__(16) __nv_bfloat16 g_B2[(size_t)DMODEL * KA2];
__device__ float2 g_CS [32 * CHUNKS * NF];
__device__ float2 g_Off[32 * CHUNKS * NF];

// ---------------- helpers ---------------------------------------------------
__device__ __forceinline__ uint32_t smem_u32(const void* p) {
    uint32_t a;
    asm("{ .reg .u64 t; cvta.to.shared.u64 t, %1; cvt.u32.u64 %0, t; }"
        : "=r"(a) : "l"(p));
    return a;
}
__device__ __forceinline__ void cp16(uint32_t dst, const void* src) {
    asm volatile("cp.async.cg.shared.global [%0], [%1], 16;"
                 :: "r"(dst), "l"(src) : "memory");
}
__device__ __forceinline__ void ldmx4(uint32_t& r0, uint32_t& r1,
                                      uint32_t& r2, uint32_t& r3, uint32_t a) {
    asm volatile("ldmatrix.sync.aligned.m8n8.x4.shared.b16 {%0,%1,%2,%3}, [%4];"
                 : "=r"(r0), "=r"(r1), "=r"(r2), "=r"(r3) : "r"(a));
}
__device__ __forceinline__ void mma16816(float* c, const uint32_t* a,
                                         const uint32_t* b) {
    asm volatile(
        "mma.sync.aligned.m16n8k16.row.col.f32.bf16.bf16.f32 "
        "{%0,%1,%2,%3}, {%4,%5,%6,%7}, {%8,%9}, {%0,%1,%2,%3};"
        : "+f"(c[0]), "+f"(c[1]), "+f"(c[2]), "+f"(c[3])
        : "r"(a[0]), "r"(a[1]), "r"(a[2]), "r"(a[3]), "r"(b[0]), "r"(b[1]));
}

// ---------------------------------------------------------------------------
// split x -> A1 = [x_hi | x_hi | x_lo]  (pairs with B1 = [W_hi | W_lo | W_hi])
// ---------------------------------------------------------------------------
__global__ void split_x(const float* __restrict__ x, __nv_bfloat16* __restrict__ A1)
{
    const size_t p = (size_t)blockIdx.x * 256 + threadIdx.x;   // < 16384*512
    const size_t row = p >> 9;
    const int dp = (int)(p & 511);
    const float2 v = *(const float2*)(x + row * 1024 + 2 * dp);
    __nv_bfloat162 h2, l2;
    h2.x = __float2bfloat16(v.x);
    h2.y = __float2bfloat16(v.y);
    l2.x = __float2bfloat16(v.x - __bfloat162float(h2.x));
    l2.y = __float2bfloat16(v.y - __bfloat162float(h2.y));
    __nv_bfloat16* base = A1 + row * KA1 + 2 * dp;
    *(__nv_bfloat162*)(base)        = h2;
    *(__nv_bfloat162*)(base + 1024) = h2;
    *(__nv_bfloat162*)(base + 2048) = l2;
}

// ---------------------------------------------------------------------------
// Wf1[d, col]  col = ((t*8+h)*65+f)*2 + {re,im}; pad cols [3120,3200) = 0
// ---------------------------------------------------------------------------
__global__ void build_wf1(const float* __restrict__ w_qkv)
{
    __shared__ float sw[3072];
    __shared__ float sc[128];
    __shared__ float ss[128];
    const int d = blockIdx.x;
    const int tid = threadIdx.x;

    for (int i = tid; i < 3072; i += 256)
        sw[i] = w_qkv[(size_t)d * 3072 + i];
    if (tid < 128) {
        float s, c;
        sincosf(6.2831853071795864769f * (float)tid / 128.0f, &s, &c);
        sc[tid] = c; ss[tid] = s;
    }
    __syncthreads();

    for (int p = tid; p < NP1 / 2; p += 256) {
        float re = 0.0f, im = 0.0f;
        if (p < 1560) {
            const int t = p / 520;
            const int rem = p % 520;
            const int h = rem / 65;
            const int f = rem % 65;
            const int base = t * 1024 + h * 128;
            int idx = 0;
            #pragma unroll 4
            for (int n = 0; n < 128; ++n) {
                const float w = sw[base + n];
                re += w * sc[idx];
                im -= w * ss[idx];
                idx = (idx + f) & 127;
            }
        }
        g_Wf1[(size_t)d * NP1 + 2 * p]     = re;
        g_Wf1[(size_t)d * NP1 + 2 * p + 1] = im;
    }
}

// ---------------------------------------------------------------------------
// Wf2[r, d'] (r < 1040), pad rows [1040,1056) = 0
// ---------------------------------------------------------------------------
__global__ void build_wf2(const float* __restrict__ w_out)
{
    __shared__ float coef[128];
    const int r = blockIdx.x;
    const int tid = threadIdx.x;

    if (r >= NC2) {
        #pragma unroll
        for (int j = 0; j < 4; ++j)
            g_Wf2[(size_t)r * DMODEL + tid + j * 256] = 0.0f;
        return;
    }
    const int h = r / 130;
    const int rr = r % 130;
    const int f = rr >> 1;
    const int part = rr & 1;

    if (tid < 128) {
        const int m = (f * tid) & 127;
        float s, c;
        sincosf(6.2831853071795864769f * (float)m / 128.0f, &s, &c);
        const float cf = (f == 0 || f == 64) ? 1.0f : 2.0f;
        coef[tid] = part ? (-(cf / 128.0f) * s) : ((cf / 128.0f) * c);
    }
    __syncthreads();

    float acc0 = 0.f, acc1 = 0.f, acc2 = 0.f, acc3 = 0.f;
    for (int n = 0; n < 128; ++n) {
        const float cv = coef[n];
        const float* wp = w_out + (size_t)(h * 128 + n) * DMODEL + tid;
        acc0 += cv * wp[0];
        acc1 += cv * wp[256];
        acc2 += cv * wp[512];
        acc3 += cv * wp[768];
    }
    g_Wf2[(size_t)r * DMODEL + tid]       = acc0;
    g_Wf2[(size_t)r * DMODEL + tid + 256] = acc1;
    g_Wf2[(size_t)r * DMODEL + tid + 512] = acc2;
    g_Wf2[(size_t)r * DMODEL + tid + 768] = acc3;
}

// ---------------------------------------------------------------------------
// transpose + bf16 split: src[R][C] fp32 -> dst[C][3R] = [hi | lo | hi]
// ---------------------------------------------------------------------------
__global__ void tsplit(const float* __restrict__ src, __nv_bfloat16* __restrict__ dst,
                       int R, int C)
{
    __shared__ float t[32][33];
    const int c0 = blockIdx.x * 32, r0 = blockIdx.y * 32;
    const int x = threadIdx.x, y = threadIdx.y;
    #pragma unroll
    for (int j = 0; j < 4; ++j)
        t[y + j * 8][x] = src[(size_t)(r0 + y + j * 8) * C + c0 + x];
    __syncthreads();
    #pragma unroll
    for (int j = 0; j < 4; ++j) {
        const int n = c0 + y + j * 8;
        const float v = t[x][y + j * 8];
        const __nv_bfloat16 h = __float2bfloat16(v);
        const __nv_bfloat16 l = __float2bfloat16(v - __bfloat162float(h));
        __nv_bfloat16* dp = dst + (size_t)n * (3 * R) + r0 + x;
        dp[0]     = h;
        dp[R]     = l;
        dp[2 * R] = h;
    }
}

// ---------------------------------------------------------------------------
// bf16 GEMM via mma.sync m16n8k16: C[M,N] = A[M,K] @ B[N,K]^T, fp32 out.
// BM=128, BN=128, BK=32, 256 threads (8 warps = 2m x 4n, warp tile 64x32),
// 4-stage cp.async pipeline, 80B-padded smem rows, occupancy 2.
// ---------------------------------------------------------------------------
#define BM 128
#define BN 128
#define BK 32
#define GSTAGES 4
#define SROW 80                       // bytes per smem row (40 bf16)
#define A_ST_B (BM * SROW)            // 10240
#define B_ST_B (BN * SROW)            // 10240
#define STG_B  (A_ST_B + B_ST_B)      // 20480
#define GSMEM  (GSTAGES * STG_B)      // 81920

__global__ __launch_bounds__(256, 2)
void gemm_mma(const __nv_bfloat16* __restrict__ A,
              const __nv_bfloat16* __restrict__ B,
              float* __restrict__ C, int N, int K, int KT)
{
    extern __shared__ char smem[];
    const uint32_t sb = smem_u32(smem);

    const int tid  = threadIdx.x;
    const int warp = tid >> 5, lane = tid & 31;
    const int wm = warp >> 2, wn = warp & 3;        // 2x4 warp grid
    const size_t row0 = (size_t)blockIdx.y * BM;
    const size_t col0 = (size_t)blockIdx.x * BN;
    const __nv_bfloat16* Ag = A + row0 * (size_t)K;
    const __nv_bfloat16* Bg = B + col0 * (size_t)K;

    // per-thread cp.async mapping: row tid>>1, two 16B chunks in one 32B half
    const int lr = tid >> 1;             // 0..127
    const int le = (tid & 1) * 16;       // elem offset 0 or 16

    float acc[4][4][4];
    #pragma unroll
    for (int i = 0; i < 4; ++i)
        #pragma unroll
        for (int j = 0; j < 4; ++j)
            #pragma unroll
            for (int q = 0; q < 4; ++q) acc[i][j][q] = 0.f;

    // prologue: stages 0..GSTAGES-2
    #pragma unroll
    for (int pc = 0; pc < GSTAGES - 1; ++pc) {
        const uint32_t st = sb + pc * STG_B;
        const int kc = pc * BK;
        cp16(st + lr * SROW + le * 2,              Ag + (size_t)lr * K + kc + le);
        cp16(st + lr * SROW + le * 2 + 16,         Ag + (size_t)lr * K + kc + le + 8);
        cp16(st + A_ST_B + lr * SROW + le * 2,     Bg + (size_t)lr * K + kc + le);
        cp16(st + A_ST_B + lr * SROW + le * 2 + 16, Bg + (size_t)lr * K + kc + le + 8);
        asm volatile("cp.async.commit_group;" ::: "memory");
    }

    // ldmatrix per-warp base addresses
    const uint32_t a_row = (uint32_t)(wm * 64 + (lane & 15));
    const uint32_t a_kk  = (uint32_t)((lane >> 4) * 8);
    const int q4 = lane >> 3;
    const uint32_t b_row = (uint32_t)(wn * 32 + (q4 >> 1) * 8 + (lane & 7));
    const uint32_t b_kk  = (uint32_t)((q4 & 1) * 8);

    for (int c = 0; c < KT; ++c) {
        const uint32_t st = sb + (c % GSTAGES) * STG_B;
        asm volatile("cp.async.wait_group %0;" :: "n"(GSTAGES - 2) : "memory");
        __syncthreads();

        const int lc = c + GSTAGES - 1;
        if (lc < KT) {
            const uint32_t stn = sb + (lc % GSTAGES) * STG_B;
            const int kc = lc * BK;
            cp16(stn + lr * SROW + le * 2,              Ag + (size_t)lr * K + kc + le);
            cp16(stn + lr * SROW + le * 2 + 16,         Ag + (size_t)lr * K + kc + le + 8);
            cp16(stn + A_ST_B + lr * SROW + le * 2,     Bg + (size_t)lr * K + kc + le);
            cp16(stn + A_ST_B + lr * SROW + le * 2 + 16, Bg + (size_t)lr * K + kc + le + 8);
        }
        asm volatile("cp.async.commit_group;" ::: "memory");

        #pragma unroll
        for (int kst = 0; kst < 2; ++kst) {
            uint32_t a[4][4], b[8];
            #pragma unroll
            for (int i = 0; i < 4; ++i)
                ldmx4(a[i][0], a[i][1], a[i][2], a[i][3],
                      st + (a_row + i * 16) * SROW + (kst * 16 + a_kk) * 2);
            #pragma unroll
            for (int p = 0; p < 2; ++p)
                ldmx4(b[4 * p], b[4 * p + 1], b[4 * p + 2], b[4 * p + 3],
                      st + A_ST_B + (b_row + p * 16) * SROW + (kst * 16 + b_kk) * 2);
            #pragma unroll
            for (int i = 0; i < 4; ++i)
                #pragma unroll
                for (int j = 0; j < 4; ++j)
                    mma16816(acc[i][j], a[i], &b[2 * j]);
        }
    }

    // epilogue: direct fp32 stores
    #pragma unroll
    for (int i = 0; i < 4; ++i) {
        const size_t r = row0 + wm * 64 + i * 16 + (lane >> 2);
        #pragma unroll
        for (int j = 0; j < 4; ++j) {
            const size_t cc = col0 + wn * 32 + j * 8 + (lane & 3) * 2;
            *(float2*)(C + r * N + cc)       = make_float2(acc[i][j][0], acc[i][j][1]);
            *(float2*)(C + (r + 8) * N + cc) = make_float2(acc[i][j][2], acc[i][j][3]);
        }
    }
}

// ---------------------------------------------------------------------------
// Chunked complex prefix scan; spec writes bf16-split A2 = [hi | hi | lo]
// g_F col layout: q base 0, k base 1040, v base 2080 (stride NP1)
// ---------------------------------------------------------------------------
__global__ void chunk_sum_kernel()
{
    const int c  = blockIdx.x;
    const int bh = blockIdx.y;
    const int f  = threadIdx.x;
    const int b = bh >> 3, h = bh & 7;
    const size_t rowbase = ((size_t)b * SEQ + (size_t)c * CLEN) * NP1;
    const int kc = 1040 + h * 130 + 2 * f;
    const int vc = 2080 + h * 130 + 2 * f;
    float sr = 0.f, si = 0.f;
    for (int s = 0; s < CLEN; ++s) {
        const float* p = g_F + rowbase + (size_t)s * NP1;
        const float2 Kv = *(const float2*)(p + kc);
        const float2 Vv = *(const float2*)(p + vc);
        sr += Kv.x * Vv.x - Kv.y * Vv.y;
        si += Kv.x * Vv.y + Kv.y * Vv.x;
    }
    g_CS[(bh * CHUNKS + c) * NF + f] = make_float2(sr, si);
}

__global__ void scan_off_kernel()
{
    const int bh = blockIdx.x;
    const int f  = threadIdx.x;
    float rr = 0.f, ri = 0.f;
    for (int c = 0; c < CHUNKS; ++c) {
        const int idx = (bh * CHUNKS + c) * NF + f;
        g_Off[idx] = make_float2(rr, ri);
        const float2 v = g_CS[idx];
        rr += v.x; ri += v.y;
    }
}

__global__ void spec_kernel()
{
    const int c  = blockIdx.x;
    const int bh = blockIdx.y;
    const int f  = threadIdx.x;              // 0..64
    const int b = bh >> 3, h = bh & 7;
    const size_t rbF = ((size_t)b * SEQ + (size_t)c * CLEN) * NP1;
    const size_t rbA = ((size_t)b * SEQ + (size_t)c * CLEN) * KA2;
    const int qc = h * 130 + 2 * f;
    const int kc = 1040 + qc;
    const int vc = 2080 + qc;
    float2 acc = g_Off[(bh * CHUNKS + c) * NF + f];
    for (int s = 0; s < CLEN; ++s) {
        const float* p = g_F + rbF + (size_t)s * NP1;
        const float2 Kv = *(const float2*)(p + kc);
        const float2 Vv = *(const float2*)(p + vc);
        const float2 Qv = *(const float2*)(p + qc);
        acc.x += Kv.x * Vv.x - Kv.y * Vv.y;
        acc.y += Kv.x * Vv.y + Kv.y * Vv.x;
        const float sx = acc.x * Qv.x + acc.y * Qv.y;   // acc * conj(Q)
        const float sy = acc.y * Qv.x - acc.x * Qv.y;
        __nv_bfloat162 h2, l2;
        h2.x = __float2bfloat16(sx);
        h2.y = __float2bfloat16(sy);
        l2.x = __float2bfloat16(sx - __bfloat162float(h2.x));
        l2.y = __float2bfloat16(sy - __bfloat162float(h2.y));
        __nv_bfloat16* dst = g_A2 + rbA + (size_t)s * KA2 + qc;
        *(__nv_bfloat162*)(dst)        = h2;
        *(__nv_bfloat162*)(dst + NPAD2)     = h2;
        *(__nv_bfloat162*)(dst + 2 * NPAD2) = l2;
    }
}

// ---------------------------------------------------------------------------
extern "C" void kernel_launch(void* const* d_in, const int* in_sizes, int n_in,
                              void* d_out, int out_size)
{
    const float* x     = (const float*)d_in[0];
    const float* w_qkv = (const float*)d_in[1];
    const float* w_out = (const float*)d_in[2];
    float* out = (float*)d_out;

    float *pWf1, *pWf2, *pF;
    __nv_bfloat16 *pA1, *pB1, *pA2, *pB2;
    cudaGetSymbolAddress((void**)&pWf1, g_Wf1);
    cudaGetSymbolAddress((void**)&pWf2, g_Wf2);
    cudaGetSymbolAddress((void**)&pF,   g_F);
    cudaGetSymbolAddress((void**)&pA1,  g_A1);
    cudaGetSymbolAddress((void**)&pB1,  g_B1);
    cudaGetSymbolAddress((void**)&pA2,  g_A2);
    cudaGetSymbolAddress((void**)&pB2,  g_B2);

    cudaFuncSetAttribute(gemm_mma, cudaFuncAttributeMaxDynamicSharedMemorySize,
                         GSMEM);

    split_x<<<32768, 256>>>(x, pA1);
    build_wf1<<<DMODEL, 256>>>(w_qkv);
    build_wf2<<<NPAD2, 256>>>(w_out);
    tsplit<<<dim3(NP1 / 32, DMODEL / 32), dim3(32, 8)>>>(pWf1, pB1, DMODEL, NP1);
    tsplit<<<dim3(DMODEL / 32, NPAD2 / 32), dim3(32, 8)>>>(pWf2, pB2, NPAD2, DMODEL);

    // GEMM1: F = x' @ Wf1'^T   (16384 x 3200, K'=3072)
    gemm_mma<<<dim3(NP1 / BN, NROWS / BM), 256, GSMEM>>>(
        pA1, pB1, pF, NP1, KA1, KA1 / BK);

    chunk_sum_kernel<<<dim3(CHUNKS, 32), NF>>>();
    scan_off_kernel<<<32, NF>>>();
    spec_kernel<<<dim3(CHUNKS, 32), NF>>>();

    // GEMM2: out = Spec' @ Wf2'^T   (16384 x 1024, K'=3168)
    gemm_mma<<<dim3(DMODEL / BN, NROWS / BM), 256, GSMEM>>>(
        pA2, pB2, out, DMODEL, KA2, KA2 / BK);
}

// round 16
// speedup vs baseline: 1.0741x; 1.0741x over previous
#include <cuda_runtime.h>
#include <cuda_bf16.h>
#include <cstdint>

// ---------------------------------------------------------------------------
// HRR self-attention:
//   GEMM1 (mma.sync bf16 x3-split): F = x @ (W_qkv . DFT)   [fp32 out]
//   chunked complex scan: Spec = cumsum_s(Fk*Fv) * conj(Fq) -> bf16 split A2
//   GEMM2 (mma.sync bf16 x3-split): out = Spec @ (iDFT . W_out)
// Engine: HMMA m16n8k16, BM=256 BN=128 BK=64, 512 thr, 3-stage cp.async.
// ---------------------------------------------------------------------------

#define BATCH 4
#define SEQ   4096
#define DMODEL 1024
#define NHEAD 8
#define NF    65
#define NROWS 16384
#define NP1   3200          // GEMM1 N (3120 used, 25*128)
#define KA1   3072          // GEMM1 K' = 3*1024 = 48*64
#define NPAD2 1088          // GEMM2 base K padded (1040 used)
#define KA2   3264          // GEMM2 K' = 3*1088 = 51*64
#define NC2   1040
#define CHUNKS 32
#define CLEN   128

// ---------------- scratch (static device globals; zero-initialized) --------
__device__ __align__(16) float  g_Wf1[(size_t)DMODEL * NP1];
__device__ __align__(16) float  g_Wf2[(size_t)NPAD2 * DMODEL];
__device__ __align__(16) float  g_F  [(size_t)NROWS * NP1];
__device__ __align__(16) __nv_bfloat16 g_A1[(size_t)NROWS * KA1];
__device__ __align__(16) __nv_bfloat16 g_B1[(size_t)NP1   * KA1];
__device__ __align__(16) __nv_bfloat16 g_A2[(size_t)NROWS * KA2];
__device__ __align__(16) __nv_bfloat16 g_B2[(size_t)DMODEL * KA2];
__device__ float2 g_CS [32 * CHUNKS * NF];
__device__ float2 g_Off[32 * CHUNKS * NF];

// ---------------- helpers ---------------------------------------------------
__device__ __forceinline__ uint32_t smem_u32(const void* p) {
    uint32_t a;
    asm("{ .reg .u64 t; cvta.to.shared.u64 t, %1; cvt.u32.u64 %0, t; }"
        : "=r"(a) : "l"(p));
    return a;
}
__device__ __forceinline__ void cp16(uint32_t dst, const void* src) {
    asm volatile("cp.async.cg.shared.global [%0], [%1], 16;"
                 :: "r"(dst), "l"(src) : "memory");
}
__device__ __forceinline__ void ldmx4(uint32_t& r0, uint32_t& r1,
                                      uint32_t& r2, uint32_t& r3, uint32_t a) {
    asm volatile("ldmatrix.sync.aligned.m8n8.x4.shared.b16 {%0,%1,%2,%3}, [%4];"
                 : "=r"(r0), "=r"(r1), "=r"(r2), "=r"(r3) : "r"(a));
}
__device__ __forceinline__ void mma16816(float* c, const uint32_t* a,
                                         const uint32_t* b) {
    asm volatile(
        "mma.sync.aligned.m16n8k16.row.col.f32.bf16.bf16.f32 "
        "{%0,%1,%2,%3}, {%4,%5,%6,%7}, {%8,%9}, {%0,%1,%2,%3};"
        : "+f"(c[0]), "+f"(c[1]), "+f"(c[2]), "+f"(c[3])
        : "r"(a[0]), "r"(a[1]), "r"(a[2]), "r"(a[3]), "r"(b[0]), "r"(b[1]));
}

// ---------------------------------------------------------------------------
// split x -> A1 = [x_hi | x_hi | x_lo]  (pairs with B1 = [W_hi | W_lo | W_hi])
// ---------------------------------------------------------------------------
__global__ void split_x(const float* __restrict__ x, __nv_bfloat16* __restrict__ A1)
{
    const size_t p = (size_t)blockIdx.x * 256 + threadIdx.x;   // < 16384*512
    const size_t row = p >> 9;
    const int dp = (int)(p & 511);
    const float2 v = *(const float2*)(x + row * 1024 + 2 * dp);
    __nv_bfloat162 h2, l2;
    h2.x = __float2bfloat16(v.x);
    h2.y = __float2bfloat16(v.y);
    l2.x = __float2bfloat16(v.x - __bfloat162float(h2.x));
    l2.y = __float2bfloat16(v.y - __bfloat162float(h2.y));
    __nv_bfloat16* base = A1 + row * KA1 + 2 * dp;
    *(__nv_bfloat162*)(base)        = h2;
    *(__nv_bfloat162*)(base + 1024) = h2;
    *(__nv_bfloat162*)(base + 2048) = l2;
}

// ---------------------------------------------------------------------------
// Wf1[d, col]  col = ((t*8+h)*65+f)*2 + {re,im}; pad cols [3120,3200) = 0
// ---------------------------------------------------------------------------
__global__ void build_wf1(const float* __restrict__ w_qkv)
{
    __shared__ float sw[3072];
    __shared__ float sc[128];
    __shared__ float ss[128];
    const int d = blockIdx.x;
    const int tid = threadIdx.x;

    for (int i = tid; i < 3072; i += 256)
        sw[i] = w_qkv[(size_t)d * 3072 + i];
    if (tid < 128) {
        float s, c;
        sincosf(6.2831853071795864769f * (float)tid / 128.0f, &s, &c);
        sc[tid] = c; ss[tid] = s;
    }
    __syncthreads();

    for (int p = tid; p < NP1 / 2; p += 256) {
        float re = 0.0f, im = 0.0f;
        if (p < 1560) {
            const int t = p / 520;
            const int rem = p % 520;
            const int h = rem / 65;
            const int f = rem % 65;
            const int base = t * 1024 + h * 128;
            int idx = 0;
            #pragma unroll 4
            for (int n = 0; n < 128; ++n) {
                const float w = sw[base + n];
                re += w * sc[idx];
                im -= w * ss[idx];
                idx = (idx + f) & 127;
            }
        }
        g_Wf1[(size_t)d * NP1 + 2 * p]     = re;
        g_Wf1[(size_t)d * NP1 + 2 * p + 1] = im;
    }
}

// ---------------------------------------------------------------------------
// Wf2[r, d'] (r < 1040), pad rows [1040,1088) = 0
// ---------------------------------------------------------------------------
__global__ void build_wf2(const float* __restrict__ w_out)
{
    __shared__ float coef[128];
    const int r = blockIdx.x;
    const int tid = threadIdx.x;

    if (r >= NC2) {
        #pragma unroll
        for (int j = 0; j < 4; ++j)
            g_Wf2[(size_t)r * DMODEL + tid + j * 256] = 0.0f;
        return;
    }
    const int h = r / 130;
    const int rr = r % 130;
    const int f = rr >> 1;
    const int part = rr & 1;

    if (tid < 128) {
        const int m = (f * tid) & 127;
        float s, c;
        sincosf(6.2831853071795864769f * (float)m / 128.0f, &s, &c);
        const float cf = (f == 0 || f == 64) ? 1.0f : 2.0f;
        coef[tid] = part ? (-(cf / 128.0f) * s) : ((cf / 128.0f) * c);
    }
    __syncthreads();

    float acc0 = 0.f, acc1 = 0.f, acc2 = 0.f, acc3 = 0.f;
    for (int n = 0; n < 128; ++n) {
        const float cv = coef[n];
        const float* wp = w_out + (size_t)(h * 128 + n) * DMODEL + tid;
        acc0 += cv * wp[0];
        acc1 += cv * wp[256];
        acc2 += cv * wp[512];
        acc3 += cv * wp[768];
    }
    g_Wf2[(size_t)r * DMODEL + tid]       = acc0;
    g_Wf2[(size_t)r * DMODEL + tid + 256] = acc1;
    g_Wf2[(size_t)r * DMODEL + tid + 512] = acc2;
    g_Wf2[(size_t)r * DMODEL + tid + 768] = acc3;
}

// ---------------------------------------------------------------------------
// transpose + bf16 split: src[R][C] fp32 -> dst[C][3R] = [hi | lo | hi]
// ---------------------------------------------------------------------------
__global__ void tsplit(const float* __restrict__ src, __nv_bfloat16* __restrict__ dst,
                       int R, int C)
{
    __shared__ float t[32][33];
    const int c0 = blockIdx.x * 32, r0 = blockIdx.y * 32;
    const int x = threadIdx.x, y = threadIdx.y;
    #pragma unroll
    for (int j = 0; j < 4; ++j)
        t[y + j * 8][x] = src[(size_t)(r0 + y + j * 8) * C + c0 + x];
    __syncthreads();
    #pragma unroll
    for (int j = 0; j < 4; ++j) {
        const int n = c0 + y + j * 8;
        const float v = t[x][y + j * 8];
        const __nv_bfloat16 h = __float2bfloat16(v);
        const __nv_bfloat16 l = __float2bfloat16(v - __bfloat162float(h));
        __nv_bfloat16* dp = dst + (size_t)n * (3 * R) + r0 + x;
        dp[0]     = h;
        dp[R]     = l;
        dp[2 * R] = h;
    }
}

// ---------------------------------------------------------------------------
// bf16 GEMM via mma.sync m16n8k16: C[M,N] = A[M,K] @ B[N,K]^T, fp32 out.
// BM=256, BN=128, BK=64, 512 threads (16 warps = 4m x 4n, warp tile 64x32),
// 3-stage cp.async pipeline, 144B-padded smem rows (conflict-free ldmatrix).
// ---------------------------------------------------------------------------
#define BM 256
#define BN 128
#define BK 64
#define GSTAGES 3
#define SROW 144                      // 64 bf16 = 128B + 16B pad
#define A_ST_B (BM * SROW)            // 36864
#define B_ST_B (BN * SROW)            // 18432
#define STG_B  (A_ST_B + B_ST_B)      // 55296
#define GSMEM  (GSTAGES * STG_B)      // 165888

__global__ __launch_bounds__(512, 1)
void gemm_mma(const __nv_bfloat16* __restrict__ A,
              const __nv_bfloat16* __restrict__ B,
              float* __restrict__ C, int N, int K, int KT)
{
    extern __shared__ char smem[];
    const uint32_t sb = smem_u32(smem);

    const int tid  = threadIdx.x;
    const int warp = tid >> 5, lane = tid & 31;
    const int wm = warp >> 2, wn = warp & 3;        // 4x4 warp grid
    const size_t row0 = (size_t)blockIdx.y * BM;
    const size_t col0 = (size_t)blockIdx.x * BN;
    const __nv_bfloat16* Ag = A + row0 * (size_t)K;
    const __nv_bfloat16* Bg = B + col0 * (size_t)K;

    // cp.async mapping: seg = 16B column segment, lrow = base row
    const int seg  = tid & 7;            // 0..7  (seg*8 elems)
    const int lrow = tid >> 3;           // 0..63

    float acc[4][4][4];
    #pragma unroll
    for (int i = 0; i < 4; ++i)
        #pragma unroll
        for (int j = 0; j < 4; ++j)
            #pragma unroll
            for (int q = 0; q < 4; ++q) acc[i][j][q] = 0.f;

    // prologue: stages 0..1
    #pragma unroll
    for (int pc = 0; pc < GSTAGES - 1; ++pc) {
        const uint32_t st = sb + pc * STG_B;
        const int kc = pc * BK;
        #pragma unroll
        for (int j = 0; j < 4; ++j)
            cp16(st + (lrow + j * 64) * SROW + seg * 16,
                 Ag + (size_t)(lrow + j * 64) * K + kc + seg * 8);
        #pragma unroll
        for (int j = 0; j < 2; ++j)
            cp16(st + A_ST_B + (lrow + j * 64) * SROW + seg * 16,
                 Bg + (size_t)(lrow + j * 64) * K + kc + seg * 8);
        asm volatile("cp.async.commit_group;" ::: "memory");
    }

    // ldmatrix per-warp base addresses
    const uint32_t a_row = (uint32_t)(wm * 64 + (lane & 15));
    const uint32_t a_kk  = (uint32_t)((lane >> 4) * 8);
    const int q4 = lane >> 3;
    const uint32_t b_row = (uint32_t)(wn * 32 + (q4 >> 1) * 8 + (lane & 7));
    const uint32_t b_kk  = (uint32_t)((q4 & 1) * 8);

    for (int c = 0; c < KT; ++c) {
        const uint32_t st = sb + (c % GSTAGES) * STG_B;
        asm volatile("cp.async.wait_group %0;" :: "n"(GSTAGES - 2) : "memory");
        __syncthreads();

        // prefetch chunk c+2 into the slot freed by chunk c-1
        const int lc = c + GSTAGES - 1;
        if (lc < KT) {
            const uint32_t stn = sb + (lc % GSTAGES) * STG_B;
            const int kc = lc * BK;
            #pragma unroll
            for (int j = 0; j < 4; ++j)
                cp16(stn + (lrow + j * 64) * SROW + seg * 16,
                     Ag + (size_t)(lrow + j * 64) * K + kc + seg * 8);
            #pragma unroll
            for (int j = 0; j < 2; ++j)
                cp16(stn + A_ST_B + (lrow + j * 64) * SROW + seg * 16,
                     Bg + (size_t)(lrow + j * 64) * K + kc + seg * 8);
        }
        asm volatile("cp.async.commit_group;" ::: "memory");

        #pragma unroll
        for (int kst = 0; kst < 4; ++kst) {
            uint32_t a[4][4], b[8];
            #pragma unroll
            for (int i = 0; i < 4; ++i)
                ldmx4(a[i][0], a[i][1], a[i][2], a[i][3],
                      st + (a_row + i * 16) * SROW + (kst * 16 + a_kk) * 2);
            #pragma unroll
            for (int p = 0; p < 2; ++p)
                ldmx4(b[4 * p], b[4 * p + 1], b[4 * p + 2], b[4 * p + 3],
                      st + A_ST_B + (b_row + p * 16) * SROW + (kst * 16 + b_kk) * 2);
            #pragma unroll
            for (int i = 0; i < 4; ++i)
                #pragma unroll
                for (int j = 0; j < 4; ++j)
                    mma16816(acc[i][j], a[i], &b[2 * j]);
        }
    }

    // epilogue: direct fp32 stores
    #pragma unroll
    for (int i = 0; i < 4; ++i) {
        const size_t r = row0 + wm * 64 + i * 16 + (lane >> 2);
        #pragma unroll
        for (int j = 0; j < 4; ++j) {
            const size_t cc = col0 + wn * 32 + j * 8 + (lane & 3) * 2;
            *(float2*)(C + r * N + cc)       = make_float2(acc[i][j][0], acc[i][j][1]);
            *(float2*)(C + (r + 8) * N + cc) = make_float2(acc[i][j][2], acc[i][j][3]);
        }
    }
}

// ---------------------------------------------------------------------------
// Chunked complex prefix scan; spec writes bf16-split A2 = [hi | hi | lo]
// g_F col layout: q base 0, k base 1040, v base 2080 (stride NP1)
// ---------------------------------------------------------------------------
__global__ void chunk_sum_kernel()
{
    const int c  = blockIdx.x;
    const int bh = blockIdx.y;
    const int f  = threadIdx.x;
    const int b = bh >> 3, h = bh & 7;
    const size_t rowbase = ((size_t)b * SEQ + (size_t)c * CLEN) * NP1;
    const int kc = 1040 + h * 130 + 2 * f;
    const int vc = 2080 + h * 130 + 2 * f;
    float sr = 0.f, si = 0.f;
    for (int s = 0; s < CLEN; ++s) {
        const float* p = g_F + rowbase + (size_t)s * NP1;
        const float2 Kv = *(const float2*)(p + kc);
        const float2 Vv = *(const float2*)(p + vc);
        sr += Kv.x * Vv.x - Kv.y * Vv.y;
        si += Kv.x * Vv.y + Kv.y * Vv.x;
    }
    g_CS[(bh * CHUNKS + c) * NF + f] = make_float2(sr, si);
}

__global__ void scan_off_kernel()
{
    const int bh = blockIdx.x;
    const int f  = threadIdx.x;
    float rr = 0.f, ri = 0.f;
    for (int c = 0; c < CHUNKS; ++c) {
        const int idx = (bh * CHUNKS + c) * NF + f;
        g_Off[idx] = make_float2(rr, ri);
        const float2 v = g_CS[idx];
        rr += v.x; ri += v.y;
    }
}

__global__ void spec_kernel()
{
    const int c  = blockIdx.x;
    const int bh = blockIdx.y;
    const int f  = threadIdx.x;              // 0..64
    const int b = bh >> 3, h = bh & 7;
    const size_t rbF = ((size_t)b * SEQ + (size_t)c * CLEN) * NP1;
    const size_t rbA = ((size_t)b * SEQ + (size_t)c * CLEN) * KA2;
    const int qc = h * 130 + 2 * f;
    const int kc = 1040 + qc;
    const int vc = 2080 + qc;
    float2 acc = g_Off[(bh * CHUNKS + c) * NF + f];
    for (int s = 0; s < CLEN; ++s) {
        const float* p = g_F + rbF + (size_t)s * NP1;
        const float2 Kv = *(const float2*)(p + kc);
        const float2 Vv = *(const float2*)(p + vc);
        const float2 Qv = *(const float2*)(p + qc);
        acc.x += Kv.x * Vv.x - Kv.y * Vv.y;
        acc.y += Kv.x * Vv.y + Kv.y * Vv.x;
        const float sx = acc.x * Qv.x + acc.y * Qv.y;   // acc * conj(Q)
        const float sy = acc.y * Qv.x - acc.x * Qv.y;
        __nv_bfloat162 h2, l2;
        h2.x = __float2bfloat16(sx);
        h2.y = __float2bfloat16(sy);
        l2.x = __float2bfloat16(sx - __bfloat162float(h2.x));
        l2.y = __float2bfloat16(sy - __bfloat162float(h2.y));
        __nv_bfloat16* dst = g_A2 + rbA + (size_t)s * KA2 + qc;
        *(__nv_bfloat162*)(dst)             = h2;
        *(__nv_bfloat162*)(dst + NPAD2)     = h2;
        *(__nv_bfloat162*)(dst + 2 * NPAD2) = l2;
    }
}

// ---------------------------------------------------------------------------
extern "C" void kernel_launch(void* const* d_in, const int* in_sizes, int n_in,
                              void* d_out, int out_size)
{
    const float* x     = (const float*)d_in[0];
    const float* w_qkv = (const float*)d_in[1];
    const float* w_out = (const float*)d_in[2];
    float* out = (float*)d_out;

    float *pWf1, *pWf2, *pF;
    __nv_bfloat16 *pA1, *pB1, *pA2, *pB2;
    cudaGetSymbolAddress((void**)&pWf1, g_Wf1);
    cudaGetSymbolAddress((void**)&pWf2, g_Wf2);
    cudaGetSymbolAddress((void**)&pF,   g_F);
    cudaGetSymbolAddress((void**)&pA1,  g_A1);
    cudaGetSymbolAddress((void**)&pB1,  g_B1);
    cudaGetSymbolAddress((void**)&pA2,  g_A2);
    cudaGetSymbolAddress((void**)&pB2,  g_B2);

    cudaFuncSetAttribute(gemm_mma, cudaFuncAttributeMaxDynamicSharedMemorySize,
                         GSMEM);

    split_x<<<32768, 256>>>(x, pA1);
    build_wf1<<<DMODEL, 256>>>(w_qkv);
    build_wf2<<<NPAD2, 256>>>(w_out);
    tsplit<<<dim3(NP1 / 32, DMODEL / 32), dim3(32, 8)>>>(pWf1, pB1, DMODEL, NP1);
    tsplit<<<dim3(DMODEL / 32, NPAD2 / 32), dim3(32, 8)>>>(pWf2, pB2, NPAD2, DMODEL);

    // GEMM1: F = x' @ Wf1'^T   (16384 x 3200, K'=3072)
    gemm_mma<<<dim3(NP1 / BN, NROWS / BM), 512, GSMEM>>>(
        pA1, pB1, pF, NP1, KA1, KA1 / BK);

    chunk_sum_kernel<<<dim3(CHUNKS, 32), NF>>>();
    scan_off_kernel<<<32, NF>>>();
    spec_kernel<<<dim3(CHUNKS, 32), NF>>>();

    // GEMM2: out = Spec' @ Wf2'^T   (16384 x 1024, K'=3264)
    gemm_mma<<<dim3(DMODEL / BN, NROWS / BM), 512, GSMEM>>>(
        pA2, pB2, out, DMODEL, KA2, KA2 / BK);
}

// round 17
// speedup vs baseline: 1.2617x; 1.1746x over previous
#include <cuda_runtime.h>
#include <cuda_bf16.h>
#include <cstdint>

// ---------------------------------------------------------------------------
// HRR self-attention:
//   GEMM1 (mma.sync bf16 x3-split): F = x @ (W_qkv . DFT)   [fp32 out]
//   chunked complex scan: Spec = cumsum_s(Fk*Fv) * conj(Fq) -> bf16 split A2
//   GEMM2 (mma.sync bf16 x3-split): out = Spec @ (iDFT . W_out)
// Engine: HMMA m16n8k16, BM=256 BN=128 BK=64, 512 thr, 3-stage cp.async,
// register double-buffered ldmatrix fragments, spread cp.async issue.
// Launch order arranged so the ncu capture slot hits gemm_mma (GEMM1).
// ---------------------------------------------------------------------------

#define BATCH 4
#define SEQ   4096
#define DMODEL 1024
#define NHEAD 8
#define NF    65
#define NROWS 16384
#define NP1   3200          // GEMM1 N (3120 used, 25*128)
#define KA1   3072          // GEMM1 K' = 3*1024 = 48*64
#define NPAD2 1088          // GEMM2 base K padded (1040 used)
#define KA2   3264          // GEMM2 K' = 3*1088 = 51*64
#define NC2   1040
#define CHUNKS 32
#define CLEN   128

// ---------------- scratch (static device globals; zero-initialized) --------
__device__ __align__(16) float  g_Wf1[(size_t)DMODEL * NP1];
__device__ __align__(16) float  g_Wf2[(size_t)NPAD2 * DMODEL];
__device__ __align__(16) float  g_F  [(size_t)NROWS * NP1];
__device__ __align__(16) __nv_bfloat16 g_A1[(size_t)NROWS * KA1];
__device__ __align__(16) __nv_bfloat16 g_B1[(size_t)NP1   * KA1];
__device__ __align__(16) __nv_bfloat16 g_A2[(size_t)NROWS * KA2];
__device__ __align__(16) __nv_bfloat16 g_B2[(size_t)DMODEL * KA2];
__device__ float2 g_CS [32 * CHUNKS * NF];
__device__ float2 g_Off[32 * CHUNKS * NF];

// ---------------- helpers ---------------------------------------------------
__device__ __forceinline__ uint32_t smem_u32(const void* p) {
    uint32_t a;
    asm("{ .reg .u64 t; cvta.to.shared.u64 t, %1; cvt.u32.u64 %0, t; }"
        : "=r"(a) : "l"(p));
    return a;
}
__device__ __forceinline__ void cp16(uint32_t dst, const void* src) {
    asm volatile("cp.async.cg.shared.global [%0], [%1], 16;"
                 :: "r"(dst), "l"(src) : "memory");
}
__device__ __forceinline__ void ldmx4(uint32_t& r0, uint32_t& r1,
                                      uint32_t& r2, uint32_t& r3, uint32_t a) {
    asm volatile("ldmatrix.sync.aligned.m8n8.x4.shared.b16 {%0,%1,%2,%3}, [%4];"
                 : "=r"(r0), "=r"(r1), "=r"(r2), "=r"(r3) : "r"(a));
}
__device__ __forceinline__ void mma16816(float* c, const uint32_t* a,
                                         const uint32_t* b) {
    asm volatile(
        "mma.sync.aligned.m16n8k16.row.col.f32.bf16.bf16.f32 "
        "{%0,%1,%2,%3}, {%4,%5,%6,%7}, {%8,%9}, {%0,%1,%2,%3};"
        : "+f"(c[0]), "+f"(c[1]), "+f"(c[2]), "+f"(c[3])
        : "r"(a[0]), "r"(a[1]), "r"(a[2]), "r"(a[3]), "r"(b[0]), "r"(b[1]));
}

// ---------------------------------------------------------------------------
// split x -> A1 = [x_hi | x_hi | x_lo]  (pairs with B1 = [W_hi | W_lo | W_hi])
// ---------------------------------------------------------------------------
__global__ void split_x(const float* __restrict__ x, __nv_bfloat16* __restrict__ A1)
{
    const size_t p = (size_t)blockIdx.x * 256 + threadIdx.x;   // < 16384*512
    const size_t row = p >> 9;
    const int dp = (int)(p & 511);
    const float2 v = *(const float2*)(x + row * 1024 + 2 * dp);
    __nv_bfloat162 h2, l2;
    h2.x = __float2bfloat16(v.x);
    h2.y = __float2bfloat16(v.y);
    l2.x = __float2bfloat16(v.x - __bfloat162float(h2.x));
    l2.y = __float2bfloat16(v.y - __bfloat162float(h2.y));
    __nv_bfloat16* base = A1 + row * KA1 + 2 * dp;
    *(__nv_bfloat162*)(base)        = h2;
    *(__nv_bfloat162*)(base + 1024) = h2;
    *(__nv_bfloat162*)(base + 2048) = l2;
}

// ---------------------------------------------------------------------------
// Wf1[d, col]  col = ((t*8+h)*65+f)*2 + {re,im}; pad cols [3120,3200) = 0
// ---------------------------------------------------------------------------
__global__ void build_wf1(const float* __restrict__ w_qkv)
{
    __shared__ float sw[3072];
    __shared__ float sc[128];
    __shared__ float ss[128];
    const int d = blockIdx.x;
    const int tid = threadIdx.x;

    for (int i = tid; i < 3072; i += 256)
        sw[i] = w_qkv[(size_t)d * 3072 + i];
    if (tid < 128) {
        float s, c;
        sincosf(6.2831853071795864769f * (float)tid / 128.0f, &s, &c);
        sc[tid] = c; ss[tid] = s;
    }
    __syncthreads();

    for (int p = tid; p < NP1 / 2; p += 256) {
        float re = 0.0f, im = 0.0f;
        if (p < 1560) {
            const int t = p / 520;
            const int rem = p % 520;
            const int h = rem / 65;
            const int f = rem % 65;
            const int base = t * 1024 + h * 128;
            int idx = 0;
            #pragma unroll 4
            for (int n = 0; n < 128; ++n) {
                const float w = sw[base + n];
                re += w * sc[idx];
                im -= w * ss[idx];
                idx = (idx + f) & 127;
            }
        }
        g_Wf1[(size_t)d * NP1 + 2 * p]     = re;
        g_Wf1[(size_t)d * NP1 + 2 * p + 1] = im;
    }
}

// ---------------------------------------------------------------------------
// Wf2[r, d'] (r < 1040), pad rows [1040,1088) = 0
// ---------------------------------------------------------------------------
__global__ void build_wf2(const float* __restrict__ w_out)
{
    __shared__ float coef[128];
    const int r = blockIdx.x;
    const int tid = threadIdx.x;

    if (r >= NC2) {
        #pragma unroll
        for (int j = 0; j < 4; ++j)
            g_Wf2[(size_t)r * DMODEL + tid + j * 256] = 0.0f;
        return;
    }
    const int h = r / 130;
    const int rr = r % 130;
    const int f = rr >> 1;
    const int part = rr & 1;

    if (tid < 128) {
        const int m = (f * tid) & 127;
        float s, c;
        sincosf(6.2831853071795864769f * (float)m / 128.0f, &s, &c);
        const float cf = (f == 0 || f == 64) ? 1.0f : 2.0f;
        coef[tid] = part ? (-(cf / 128.0f) * s) : ((cf / 128.0f) * c);
    }
    __syncthreads();

    float acc0 = 0.f, acc1 = 0.f, acc2 = 0.f, acc3 = 0.f;
    for (int n = 0; n < 128; ++n) {
        const float cv = coef[n];
        const float* wp = w_out + (size_t)(h * 128 + n) * DMODEL + tid;
        acc0 += cv * wp[0];
        acc1 += cv * wp[256];
        acc2 += cv * wp[512];
        acc3 += cv * wp[768];
    }
    g_Wf2[(size_t)r * DMODEL + tid]       = acc0;
    g_Wf2[(size_t)r * DMODEL + tid + 256] = acc1;
    g_Wf2[(size_t)r * DMODEL + tid + 512] = acc2;
    g_Wf2[(size_t)r * DMODEL + tid + 768] = acc3;
}

// ---------------------------------------------------------------------------
// transpose + bf16 split: src[R][C] fp32 -> dst[C][3R] = [hi | lo | hi]
// ---------------------------------------------------------------------------
__global__ void tsplit(const float* __restrict__ src, __nv_bfloat16* __restrict__ dst,
                       int R, int C)
{
    __shared__ float t[32][33];
    const int c0 = blockIdx.x * 32, r0 = blockIdx.y * 32;
    const int x = threadIdx.x, y = threadIdx.y;
    #pragma unroll
    for (int j = 0; j < 4; ++j)
        t[y + j * 8][x] = src[(size_t)(r0 + y + j * 8) * C + c0 + x];
    __syncthreads();
    #pragma unroll
    for (int j = 0; j < 4; ++j) {
        const int n = c0 + y + j * 8;
        const float v = t[x][y + j * 8];
        const __nv_bfloat16 h = __float2bfloat16(v);
        const __nv_bfloat16 l = __float2bfloat16(v - __bfloat162float(h));
        __nv_bfloat16* dp = dst + (size_t)n * (3 * R) + r0 + x;
        dp[0]     = h;
        dp[R]     = l;
        dp[2 * R] = h;
    }
}

// ---------------------------------------------------------------------------
// bf16 GEMM via mma.sync m16n8k16: C[M,N] = A[M,K] @ B[N,K]^T, fp32 out.
// BM=256, BN=128, BK=64, 512 threads (16 warps = 4m x 4n, warp tile 64x32),
// 3-stage cp.async, reg double-buffered frags, cp.async spread over kst.
// ---------------------------------------------------------------------------
#define BM 256
#define BN 128
#define BK 64
#define GSTAGES 3
#define SROW 144                      // 64 bf16 = 128B + 16B pad
#define A_ST_B (BM * SROW)            // 36864
#define B_ST_B (BN * SROW)            // 18432
#define STG_B  (A_ST_B + B_ST_B)      // 55296
#define GSMEM  (GSTAGES * STG_B)      // 165888

__global__ __launch_bounds__(512, 1)
void gemm_mma(const __nv_bfloat16* __restrict__ A,
              const __nv_bfloat16* __restrict__ B,
              float* __restrict__ C, int N, int K, int KT)
{
    extern __shared__ char smem[];
    const uint32_t sb = smem_u32(smem);

    const int tid  = threadIdx.x;
    const int warp = tid >> 5, lane = tid & 31;
    const int wm = warp >> 2, wn = warp & 3;        // 4x4 warp grid
    const size_t row0 = (size_t)blockIdx.y * BM;
    const size_t col0 = (size_t)blockIdx.x * BN;
    const __nv_bfloat16* Ag = A + row0 * (size_t)K;
    const __nv_bfloat16* Bg = B + col0 * (size_t)K;

    // cp.async mapping: seg = 16B column segment, lrow = base row
    const int seg  = tid & 7;            // 0..7  (seg*8 elems)
    const int lrow = tid >> 3;           // 0..63

    float acc[4][4][4];
    #pragma unroll
    for (int i = 0; i < 4; ++i)
        #pragma unroll
        for (int j = 0; j < 4; ++j)
            #pragma unroll
            for (int q = 0; q < 4; ++q) acc[i][j][q] = 0.f;

    // prologue: stages 0..1
    #pragma unroll
    for (int pc = 0; pc < GSTAGES - 1; ++pc) {
        const uint32_t st = sb + pc * STG_B;
        const int kc = pc * BK;
        #pragma unroll
        for (int j = 0; j < 4; ++j)
            cp16(st + (lrow + j * 64) * SROW + seg * 16,
                 Ag + (size_t)(lrow + j * 64) * K + kc + seg * 8);
        #pragma unroll
        for (int j = 0; j < 2; ++j)
            cp16(st + A_ST_B + (lrow + j * 64) * SROW + seg * 16,
                 Bg + (size_t)(lrow + j * 64) * K + kc + seg * 8);
        asm volatile("cp.async.commit_group;" ::: "memory");
    }

    // ldmatrix per-warp base addresses
    const uint32_t a_row = (uint32_t)(wm * 64 + (lane & 15));
    const uint32_t a_kk  = (uint32_t)((lane >> 4) * 8);
    const int q4 = lane >> 3;
    const uint32_t b_row = (uint32_t)(wn * 32 + (q4 >> 1) * 8 + (lane & 7));
    const uint32_t b_kk  = (uint32_t)((q4 & 1) * 8);

    for (int c = 0; c < KT; ++c) {
        const uint32_t st = sb + (c % GSTAGES) * STG_B;
        asm volatile("cp.async.wait_group %0;" :: "n"(GSTAGES - 2) : "memory");
        __syncthreads();

        const int lc = c + GSTAGES - 1;
        const bool pf = lc < KT;
        const uint32_t stn = sb + (lc % GSTAGES) * STG_B;
        const int kc = lc * BK;

        uint32_t abuf[2][4][4], bbuf[2][8];
        // load kst=0 fragments into buffer 0
        #pragma unroll
        for (int i = 0; i < 4; ++i)
            ldmx4(abuf[0][i][0], abuf[0][i][1], abuf[0][i][2], abuf[0][i][3],
                  st + (a_row + i * 16) * SROW + a_kk * 2);
        #pragma unroll
        for (int p = 0; p < 2; ++p)
            ldmx4(bbuf[0][4 * p], bbuf[0][4 * p + 1],
                  bbuf[0][4 * p + 2], bbuf[0][4 * p + 3],
                  st + A_ST_B + (b_row + p * 16) * SROW + b_kk * 2);

        #pragma unroll
        for (int kst = 0; kst < 4; ++kst) {
            const int cur = kst & 1, nxt = cur ^ 1;
            // prefetch next kst's fragments before this kst's MMAs
            if (kst < 3) {
                #pragma unroll
                for (int i = 0; i < 4; ++i)
                    ldmx4(abuf[nxt][i][0], abuf[nxt][i][1],
                          abuf[nxt][i][2], abuf[nxt][i][3],
                          st + (a_row + i * 16) * SROW + ((kst + 1) * 16 + a_kk) * 2);
                #pragma unroll
                for (int p = 0; p < 2; ++p)
                    ldmx4(bbuf[nxt][4 * p], bbuf[nxt][4 * p + 1],
                          bbuf[nxt][4 * p + 2], bbuf[nxt][4 * p + 3],
                          st + A_ST_B + (b_row + p * 16) * SROW
                             + ((kst + 1) * 16 + b_kk) * 2);
            }
            // spread global prefetch of chunk c+2 across kst 0..2
            if (pf) {
                if (kst == 0) {
                    cp16(stn + lrow * SROW + seg * 16,
                         Ag + (size_t)lrow * K + kc + seg * 8);
                    cp16(stn + (lrow + 64) * SROW + seg * 16,
                         Ag + (size_t)(lrow + 64) * K + kc + seg * 8);
                } else if (kst == 1) {
                    cp16(stn + (lrow + 128) * SROW + seg * 16,
                         Ag + (size_t)(lrow + 128) * K + kc + seg * 8);
                    cp16(stn + (lrow + 192) * SROW + seg * 16,
                         Ag + (size_t)(lrow + 192) * K + kc + seg * 8);
                } else if (kst == 2) {
                    cp16(stn + A_ST_B + lrow * SROW + seg * 16,
                         Bg + (size_t)lrow * K + kc + seg * 8);
                    cp16(stn + A_ST_B + (lrow + 64) * SROW + seg * 16,
                         Bg + (size_t)(lrow + 64) * K + kc + seg * 8);
                }
            }
            if (kst == 3)
                asm volatile("cp.async.commit_group;" ::: "memory");

            #pragma unroll
            for (int i = 0; i < 4; ++i)
                #pragma unroll
                for (int j = 0; j < 4; ++j)
                    mma16816(acc[i][j], abuf[cur][i], &bbuf[cur][2 * j]);
        }
    }

    // epilogue: direct fp32 stores
    #pragma unroll
    for (int i = 0; i < 4; ++i) {
        const size_t r = row0 + wm * 64 + i * 16 + (lane >> 2);
        #pragma unroll
        for (int j = 0; j < 4; ++j) {
            const size_t cc = col0 + wn * 32 + j * 8 + (lane & 3) * 2;
            *(float2*)(C + r * N + cc)       = make_float2(acc[i][j][0], acc[i][j][1]);
            *(float2*)(C + (r + 8) * N + cc) = make_float2(acc[i][j][2], acc[i][j][3]);
        }
    }
}

// ---------------------------------------------------------------------------
// Chunked complex prefix scan; spec writes bf16-split A2 = [hi | hi | lo]
// g_F col layout: q base 0, k base 1040, v base 2080 (stride NP1)
// ---------------------------------------------------------------------------
__global__ void chunk_sum_kernel()
{
    const int c  = blockIdx.x;
    const int bh = blockIdx.y;
    const int f  = threadIdx.x;
    const int b = bh >> 3, h = bh & 7;
    const size_t rowbase = ((size_t)b * SEQ + (size_t)c * CLEN) * NP1;
    const int kc = 1040 + h * 130 + 2 * f;
    const int vc = 2080 + h * 130 + 2 * f;
    float sr = 0.f, si = 0.f;
    for (int s = 0; s < CLEN; ++s) {
        const float* p = g_F + rowbase + (size_t)s * NP1;
        const float2 Kv = *(const float2*)(p + kc);
        const float2 Vv = *(const float2*)(p + vc);
        sr += Kv.x * Vv.x - Kv.y * Vv.y;
        si += Kv.x * Vv.y + Kv.y * Vv.x;
    }
    g_CS[(bh * CHUNKS + c) * NF + f] = make_float2(sr, si);
}

__global__ void scan_off_kernel()
{
    const int bh = blockIdx.x;
    const int f  = threadIdx.x;
    float rr = 0.f, ri = 0.f;
    for (int c = 0; c < CHUNKS; ++c) {
        const int idx = (bh * CHUNKS + c) * NF + f;
        g_Off[idx] = make_float2(rr, ri);
        const float2 v = g_CS[idx];
        rr += v.x; ri += v.y;
    }
}

__global__ void spec_kernel()
{
    const int c  = blockIdx.x;
    const int bh = blockIdx.y;
    const int f  = threadIdx.x;              // 0..64
    const int b = bh >> 3, h = bh & 7;
    const size_t rbF = ((size_t)b * SEQ + (size_t)c * CLEN) * NP1;
    const size_t rbA = ((size_t)b * SEQ + (size_t)c * CLEN) * KA2;
    const int qc = h * 130 + 2 * f;
    const int kc = 1040 + qc;
    const int vc = 2080 + qc;
    float2 acc = g_Off[(bh * CHUNKS + c) * NF + f];
    for (int s = 0; s < CLEN; ++s) {
        const float* p = g_F + rbF + (size_t)s * NP1;
        const float2 Kv = *(const float2*)(p + kc);
        const float2 Vv = *(const float2*)(p + vc);
        const float2 Qv = *(const float2*)(p + qc);
        acc.x += Kv.x * Vv.x - Kv.y * Vv.y;
        acc.y += Kv.x * Vv.y + Kv.y * Vv.x;
        const float sx = acc.x * Qv.x + acc.y * Qv.y;   // acc * conj(Q)
        const float sy = acc.y * Qv.x - acc.x * Qv.y;
        __nv_bfloat162 h2, l2;
        h2.x = __float2bfloat16(sx);
        h2.y = __float2bfloat16(sy);
        l2.x = __float2bfloat16(sx - __bfloat162float(h2.x));
        l2.y = __float2bfloat16(sy - __bfloat162float(h2.y));
        __nv_bfloat16* dst = g_A2 + rbA + (size_t)s * KA2 + qc;
        *(__nv_bfloat162*)(dst)             = h2;
        *(__nv_bfloat162*)(dst + NPAD2)     = h2;
        *(__nv_bfloat162*)(dst + 2 * NPAD2) = l2;
    }
}

// ---------------------------------------------------------------------------
extern "C" void kernel_launch(void* const* d_in, const int* in_sizes, int n_in,
                              void* d_out, int out_size)
{
    const float* x     = (const float*)d_in[0];
    const float* w_qkv = (const float*)d_in[1];
    const float* w_out = (const float*)d_in[2];
    float* out = (float*)d_out;

    float *pWf1, *pWf2, *pF;
    __nv_bfloat16 *pA1, *pB1, *pA2, *pB2;
    cudaGetSymbolAddress((void**)&pWf1, g_Wf1);
    cudaGetSymbolAddress((void**)&pWf2, g_Wf2);
    cudaGetSymbolAddress((void**)&pF,   g_F);
    cudaGetSymbolAddress((void**)&pA1,  g_A1);
    cudaGetSymbolAddress((void**)&pB1,  g_B1);
    cudaGetSymbolAddress((void**)&pA2,  g_A2);
    cudaGetSymbolAddress((void**)&pB2,  g_B2);

    cudaFuncSetAttribute(gemm_mma, cudaFuncAttributeMaxDynamicSharedMemorySize,
                         GSMEM);

    // Launch order puts GEMM1 at the ncu capture slot (4th launch),
    // dependencies preserved on the single stream.
    split_x<<<32768, 256>>>(x, pA1);                                     // 0
    build_wf1<<<DMODEL, 256>>>(w_qkv);                                   // 1
    tsplit<<<dim3(NP1 / 32, DMODEL / 32), dim3(32, 8)>>>(pWf1, pB1,
                                                         DMODEL, NP1);   // 2
    // GEMM1: F = x' @ Wf1'^T   (16384 x 3200, K'=3072)
    gemm_mma<<<dim3(NP1 / BN, NROWS / BM), 512, GSMEM>>>(
        pA1, pB1, pF, NP1, KA1, KA1 / BK);                               // 3

    build_wf2<<<NPAD2, 256>>>(w_out);                                    // 4
    tsplit<<<dim3(DMODEL / 32, NPAD2 / 32), dim3(32, 8)>>>(pWf2, pB2,
                                                           NPAD2, DMODEL);

    chunk_sum_kernel<<<dim3(CHUNKS, 32), NF>>>();
    scan_off_kernel<<<32, NF>>>();
    spec_kernel<<<dim3(CHUNKS, 32), NF>>>();

    // GEMM2: out = Spec' @ Wf2'^T   (16384 x 1024, K'=3264)
    gemm_mma<<<dim3(DMODEL / BN, NROWS / BM), 512, GSMEM>>>(
        pA2, pB2, out, DMODEL, KA2, KA2 / BK);
}